// round 13
// baseline (speedup 1.0000x reference)
#include <cuda_runtime.h>
#include <cuda_fp16.h>
#include <cstdint>

#define D       128
#define NREL    48
#define NB      8
#define NENT    50000
#define NSPEC   64
#define NEDGE   600000
#define CAP     64                  // per-dst bucket capacity (Poisson(12) tail ~0)
#define KACC    1024
#define KTOT    1152
#define MTILE   128
#define NTIL    391                 // ceil(50000/128)
#define MPAD    (NTIL * MTILE)      // 50048
#define KC      16
#define NCH     (KTOT / KC)         // 72
#define SSTR    24                  // smem row stride (halves): 48B, LDSM conflict-free
#define NSTG    4                   // 4-stage pipeline: 48KB static smem exactly

// ---------------- device scratch ----------------
__device__ int    g_cur[NENT];                 // bucket cursors (init n*CAP)
__device__ int    g_pk[NENT * CAP];            // bucketed packed (src | type<<16)
__device__ __half g_xh[(size_t)NENT * D];      // x in fp16
__device__ __half g_A[(size_t)MPAD * KTOT];    // fp16 A; pad rows stay zero
__device__ __half g_Bh[(size_t)D * KTOT];      // B^T [n][k] fp16

__device__ __forceinline__ int clampi(int v, int lo, int hi) {
    return v < lo ? lo : (v > hi ? hi : v);
}
__device__ __forceinline__ uint32_t smem_u32(const void* p) {
    uint32_t a;
    asm("{ .reg .u64 t; cvta.to.shared.u64 t, %1; cvt.u32.u64 %0, t; }"
        : "=r"(a) : "l"(p));
    return a;
}
__device__ __forceinline__ void ldsm4(uint32_t* r, uint32_t addr) {
    asm volatile("ldmatrix.sync.aligned.m8n8.x4.shared.b16 {%0,%1,%2,%3}, [%4];"
        : "=r"(r[0]), "=r"(r[1]), "=r"(r[2]), "=r"(r[3]) : "r"(addr));
}
__device__ __forceinline__ void mma_f16(float* c, const uint32_t* a,
                                        const uint32_t* b) {
    asm volatile(
        "mma.sync.aligned.m16n8k16.row.col.f32.f16.f16.f32 "
        "{%0,%1,%2,%3}, {%4,%5,%6,%7}, {%8,%9}, {%0,%1,%2,%3};"
        : "+f"(c[0]), "+f"(c[1]), "+f"(c[2]), "+f"(c[3])
        : "r"(a[0]), "r"(a[1]), "r"(a[2]), "r"(a[3]), "r"(b[0]), "r"(b[1]));
}
__device__ __forceinline__ void cp16(uint32_t dst, const void* src) {
    asm volatile("cp.async.cg.shared.global [%0], [%1], 16;"
                 :: "r"(dst), "l"(src) : "memory");
}
__device__ __forceinline__ void cp_commit() {
    asm volatile("cp.async.commit_group;" ::: "memory");
}
template <int N>
__device__ __forceinline__ void cp_wait() {
    asm volatile("cp.async.wait_group %0;" :: "n"(N) : "memory");
}
// packed f32x2 helpers (base sm_100-family PTX, valid at compute_103)
__device__ __forceinline__ unsigned long long pack2(float lo, float hi) {
    unsigned long long r;
    asm("mov.b64 %0, {%1, %2};" : "=l"(r) : "f"(lo), "f"(hi));
    return r;
}
__device__ __forceinline__ void fma2(unsigned long long& acc,
                                     unsigned long long a, unsigned long long b) {
    asm("fma.rn.f32x2 %0, %1, %2, %0;" : "+l"(acc) : "l"(a), "l"(b));
}
__device__ __forceinline__ float2 unpack2(unsigned long long v) {
    float lo, hi;
    asm("mov.b64 {%0, %1}, %2;" : "=f"(lo), "=f"(hi) : "l"(v));
    return make_float2(lo, hi);
}

// ---------------- fused prep: x->fp16, B^T fp16, special concat, cursor init -
#define NPX   (NENT * D / 2)          // 3,200,000 half2 pairs
#define NPB   (D * KTOT)              // 147,456
#define NPS   (NSPEC * D)             // 8,192
#define NPZ   (NENT)                  // g_cur init
#define NPTOT (NPX + NPB + NPS + NPZ)
__global__ void k_prep(const float* __restrict__ x,
                       const float* __restrict__ basis,
                       const float* __restrict__ root,
                       const float* __restrict__ spec,
                       float* __restrict__ out) {
    int i = blockIdx.x * blockDim.x + threadIdx.x;
    if (i < NPX) {
        float2 v = *((const float2*)x + i);
        *((__half2*)g_xh + i) = __float22half2_rn(v);
        return;
    }
    int j = i - NPX;
    if (j < NPB) {
        int n = j / KTOT, k = j % KTOT;
        float v = (k < KACC) ? basis[(size_t)k * D + n]
                             : root[(size_t)(k - KACC) * D + n];
        g_Bh[j] = __float2half_rn(v);
        return;
    }
    int s = j - NPB;
    if (s < NPS) { out[(size_t)NENT * D + s] = spec[s]; return; }
    int z = s - NPS;
    if (z < NENT) g_cur[z] = z * CAP;
}

// ---------------- single-pass bucketed scatter ----------------
__global__ void k_scatter(const int* __restrict__ ei, const int* __restrict__ et) {
    int e = blockIdx.x * blockDim.x + threadIdx.x;
    if (e >= NEDGE) return;
    int src = clampi(ei[e], 0, NENT - 1);
    int dst = clampi(ei[NEDGE + e], 0, NENT - 1);
    int typ = clampi(et[e], 0, NREL - 1);
    int pos = atomicAdd(&g_cur[dst], 1);
    if (pos < (dst + 1) * CAP)                  // clamp vs bucket overflow
        g_pk[pos] = src | (typ << 16);
}

// ---------------- aggregation: warp per node, pre-scaled packed coeffs -------
__global__ __launch_bounds__(256)
void k_agg(const float* __restrict__ comp) {
    __shared__ float comps[NREL * NB];
    __shared__ int   cnts[8][NREL];
    __shared__ unsigned long long wc[8][NREL * NB];   // 24 KB: (c,c) packed pairs
    int tid = threadIdx.x;
    for (int t = tid; t < NREL * NB; t += 256) comps[t] = comp[t];
    __syncthreads();

    int w = tid >> 5, lane = tid & 31;
    int n = blockIdx.x * 8 + w;
    if (n >= NENT) return;

    int s = n * CAP;
    int e = g_cur[n];
    if (e > s + CAP) e = s + CAP;

    for (int t = lane; t < NREL; t += 32) cnts[w][t] = 0;
    __syncwarp();
    for (int idx = s + lane; idx < e; idx += 32)
        atomicAdd(&cnts[w][(g_pk[idx] >> 16) & 0x3F], 1);
    __syncwarp();
    // wc[typ*NB+b] = comp[typ][b]/cnt[typ], packed as (c,c)
    for (int t = lane; t < NREL * NB; t += 32) {
        int cnt = cnts[w][t >> 3];
        float inv = (cnt > 0) ? 1.0f / (float)cnt : 0.f;
        float c = comps[t] * inv;
        wc[w][t] = pack2(c, c);
    }
    __syncwarp();

    unsigned long long av01[NB], av23[NB];
    unsigned long long zero = pack2(0.f, 0.f);
#pragma unroll
    for (int b = 0; b < NB; b++) { av01[b] = zero; av23[b] = zero; }

    // software-pipelined edge loop (1-deep prefetch)
    if (s < e) {
        int   pk = g_pk[s];
        uint2 u  = *(const uint2*)(g_xh + (size_t)(pk & 0xFFFF) * D + lane * 4);
        for (int idx = s; idx < e; idx++) {
            int   npk = 0;
            uint2 nu  = make_uint2(0u, 0u);
            if (idx + 1 < e) {
                npk = g_pk[idx + 1];
                nu  = *(const uint2*)(g_xh + (size_t)(npk & 0xFFFF) * D + lane * 4);
            }
            int typ = (pk >> 16) & 0x3F;
            float2 x01 = __half22float2(*(__half2*)&u.x);
            float2 x23 = __half22float2(*(__half2*)&u.y);
            unsigned long long px01 = pack2(x01.x, x01.y);
            unsigned long long px23 = pack2(x23.x, x23.y);
            const unsigned long long* wct = &wc[w][typ * NB];
#pragma unroll
            for (int b = 0; b < NB; b++) {
                unsigned long long cc = wct[b];
                fma2(av01[b], cc, px01);
                fma2(av23[b], cc, px23);
            }
            pk = npk;
            u  = nu;
        }
    }

    size_t rb = (size_t)n * KTOT;
#pragma unroll
    for (int b = 0; b < NB; b++) {
        float2 a01 = unpack2(av01[b]);
        float2 a23 = unpack2(av23[b]);
        uint2 u;
        *(__half2*)&u.x = __float22half2_rn(a01);
        *(__half2*)&u.y = __float22half2_rn(a23);
        *(uint2*)(g_A + rb + b * D + lane * 4) = u;
    }
    *(uint2*)(g_A + rb + KACC + lane * 4) =
        *(const uint2*)(g_xh + (size_t)n * D + lane * 4);
}

// ---------------- fp16 HMMA GEMM: 4-stage cp.async, reverse tile order -------
__global__ __launch_bounds__(256, 2)
void k_gemm(const float* __restrict__ bias, float* __restrict__ out) {
    __shared__ __align__(16) __half sA[NSTG][MTILE][SSTR];   // 24 KB
    __shared__ __align__(16) __half sB[NSTG][D][SSTR];       // 24 KB

    int tid = threadIdx.x, wid = tid >> 5, lane = tid & 31;
    // reverse tile order: read the most-recently-written (L2-hot) A rows first
    int m0 = (NTIL - 1 - blockIdx.x) * MTILE;
    int wm = wid & 1;
    int wn = wid >> 1;
    int pr = tid >> 1, pq = tid & 1;   // prefetch: 128 rows x 2 chunks of 16B

    float c[4][4][4];
#pragma unroll
    for (int mt = 0; mt < 4; mt++)
#pragma unroll
        for (int nt = 0; nt < 4; nt++)
#pragma unroll
            for (int r = 0; r < 4; r++) c[mt][nt][r] = 0.f;

    // prologue: prefetch chunks 0..2
#pragma unroll
    for (int p = 0; p < NSTG - 1; p++) {
        int kc = p * KC;
        cp16(smem_u32(&sA[p][pr][pq * 8]),
             g_A + (size_t)(m0 + pr) * KTOT + kc + pq * 8);
        cp16(smem_u32(&sB[p][pr][pq * 8]),
             g_Bh + (size_t)pr * KTOT + kc + pq * 8);
        cp_commit();
    }

    for (int ch = 0; ch < NCH; ch++) {
        cp_wait<NSTG - 2>();
        __syncthreads();

        int st = ch & (NSTG - 1);
        uint32_t a[4][4], b[2][4];
        int arow = wm * 64 + (lane & 15);
        int acol = (lane >> 4) * 8;
#pragma unroll
        for (int mt = 0; mt < 4; mt++)
            ldsm4(a[mt], smem_u32(&sA[st][arow + mt * 16][acol]));
        int brow = wn * 32 + (lane & 7) + ((lane >> 4) << 3);
        int bcol = ((lane >> 3) & 1) * 8;
#pragma unroll
        for (int p = 0; p < 2; p++)
            ldsm4(b[p], smem_u32(&sB[st][brow + p * 16][bcol]));
#pragma unroll
        for (int mt = 0; mt < 4; mt++)
#pragma unroll
            for (int nt = 0; nt < 4; nt++)
                mma_f16(c[mt][nt], a[mt], &b[nt >> 1][(nt & 1) * 2]);

        int nc = ch + NSTG - 1;
        if (nc < NCH) {
            int ns = nc & (NSTG - 1);
            int kc = nc * KC;
            cp16(smem_u32(&sA[ns][pr][pq * 8]),
                 g_A + (size_t)(m0 + pr) * KTOT + kc + pq * 8);
            cp16(smem_u32(&sB[ns][pr][pq * 8]),
                 g_Bh + (size_t)pr * KTOT + kc + pq * 8);
        }
        cp_commit();
    }
    cp_wait<0>();

    // epilogue: frag (m16n8): lane owns rows l/4, l/4+8; cols (l&3)*2, +1
#pragma unroll
    for (int mt = 0; mt < 4; mt++) {
#pragma unroll
        for (int nt = 0; nt < 4; nt++) {
            int m = m0 + wm * 64 + mt * 16 + (lane >> 2);
            int n = wn * 32 + nt * 8 + (lane & 3) * 2;
            float b0 = __ldg(bias + n), b1 = __ldg(bias + n + 1);
            if (m < NENT) {
                float2 v = make_float2(c[mt][nt][0] + b0, c[mt][nt][1] + b1);
                *(float2*)(out + (size_t)m * D + n) = v;
            }
            if (m + 8 < NENT) {
                float2 v = make_float2(c[mt][nt][2] + b0, c[mt][nt][3] + b1);
                *(float2*)(out + (size_t)(m + 8) * D + n) = v;
            }
        }
    }
}

// ---------------- launch ----------------
extern "C" void kernel_launch(void* const* d_in, const int* in_sizes, int n_in,
                              void* d_out, int out_size) {
    const int*   ei    = (const int*)d_in[0];
    const int*   et    = (const int*)d_in[1];
    const float* x     = (const float*)d_in[2];
    const float* basis = (const float*)d_in[3];
    const float* comp  = (const float*)d_in[4];
    const float* root  = (const float*)d_in[5];
    const float* bias  = (const float*)d_in[6];
    const float* spec  = (const float*)d_in[7];
    float*       out   = (float*)d_out;

    k_prep<<<(NPTOT + 255) / 256, 256>>>(x, basis, root, spec, out);
    k_scatter<<<(NEDGE + 255) / 256, 256>>>(ei, et);
    k_agg<<<(NENT + 7) / 8, 256>>>(comp);
    k_gemm<<<NTIL, 256>>>(bias, out);
}

// round 14
// speedup vs baseline: 1.1014x; 1.1014x over previous
#include <cuda_runtime.h>
#include <cuda_fp16.h>
#include <cstdint>

#define D       128
#define NREL    48
#define NB      8
#define NENT    50000
#define NSPEC   64
#define NEDGE   600000
#define CAP     64                  // per-dst bucket capacity (Poisson(12) tail ~0)
#define KACC    1024
#define KTOT    1152
#define MTILE   128
#define NTIL    391                 // ceil(50000/128)
#define MPAD    (NTIL * MTILE)      // 50048
#define KC      32
#define NCH     (KTOT / KC)         // 36
#define SSTR    40                  // smem row stride (halves): 80B, LDSM-validated

// ---------------- device scratch ----------------
__device__ int    g_cur[NENT];                 // bucket cursors (init n*CAP)
__device__ int    g_pk[NENT * CAP];            // bucketed packed (src | type<<16)
__device__ __half g_xh[(size_t)NENT * D];      // x in fp16
__device__ __half g_A[(size_t)MPAD * KTOT];    // fp16 A; pad rows stay zero
__device__ __half g_Bh[(size_t)D * KTOT];      // B^T [n][k] fp16

__device__ __forceinline__ int clampi(int v, int lo, int hi) {
    return v < lo ? lo : (v > hi ? hi : v);
}
__device__ __forceinline__ uint32_t smem_u32(const void* p) {
    uint32_t a;
    asm("{ .reg .u64 t; cvta.to.shared.u64 t, %1; cvt.u32.u64 %0, t; }"
        : "=r"(a) : "l"(p));
    return a;
}
__device__ __forceinline__ void ldsm4(uint32_t* r, uint32_t addr) {
    asm volatile("ldmatrix.sync.aligned.m8n8.x4.shared.b16 {%0,%1,%2,%3}, [%4];"
        : "=r"(r[0]), "=r"(r[1]), "=r"(r[2]), "=r"(r[3]) : "r"(addr));
}
__device__ __forceinline__ void mma_f16(float* c, const uint32_t* a,
                                        const uint32_t* b) {
    asm volatile(
        "mma.sync.aligned.m16n8k16.row.col.f32.f16.f16.f32 "
        "{%0,%1,%2,%3}, {%4,%5,%6,%7}, {%8,%9}, {%0,%1,%2,%3};"
        : "+f"(c[0]), "+f"(c[1]), "+f"(c[2]), "+f"(c[3])
        : "r"(a[0]), "r"(a[1]), "r"(a[2]), "r"(a[3]), "r"(b[0]), "r"(b[1]));
}
__device__ __forceinline__ void cp16(uint32_t dst, const void* src) {
    asm volatile("cp.async.cg.shared.global [%0], [%1], 16;"
                 :: "r"(dst), "l"(src) : "memory");
}
__device__ __forceinline__ void cp_commit() {
    asm volatile("cp.async.commit_group;" ::: "memory");
}
template <int N>
__device__ __forceinline__ void cp_wait() {
    asm volatile("cp.async.wait_group %0;" :: "n"(N) : "memory");
}
// packed f32x2 helpers (base sm_100-family PTX, valid at compute_103)
__device__ __forceinline__ unsigned long long pack2(float lo, float hi) {
    unsigned long long r;
    asm("mov.b64 %0, {%1, %2};" : "=l"(r) : "f"(lo), "f"(hi));
    return r;
}
__device__ __forceinline__ void fma2(unsigned long long& acc,
                                     unsigned long long a, unsigned long long b) {
    asm("fma.rn.f32x2 %0, %1, %2, %0;" : "+l"(acc) : "l"(a), "l"(b));
}
__device__ __forceinline__ float2 unpack2(unsigned long long v) {
    float lo, hi;
    asm("mov.b64 {%0, %1}, %2;" : "=f"(lo), "=f"(hi) : "l"(v));
    return make_float2(lo, hi);
}

// ---------------- fused prep: x->fp16, B^T fp16, special concat, cursor init -
#define NPX   (NENT * D / 2)          // 3,200,000 half2 pairs
#define NPB   (D * KTOT)              // 147,456
#define NPS   (NSPEC * D)             // 8,192
#define NPZ   (NENT)                  // g_cur init
#define NPTOT (NPX + NPB + NPS + NPZ)
__global__ void k_prep(const float* __restrict__ x,
                       const float* __restrict__ basis,
                       const float* __restrict__ root,
                       const float* __restrict__ spec,
                       float* __restrict__ out) {
    int i = blockIdx.x * blockDim.x + threadIdx.x;
    if (i < NPX) {
        float2 v = *((const float2*)x + i);
        *((__half2*)g_xh + i) = __float22half2_rn(v);
        return;
    }
    int j = i - NPX;
    if (j < NPB) {
        int n = j / KTOT, k = j % KTOT;
        float v = (k < KACC) ? basis[(size_t)k * D + n]
                             : root[(size_t)(k - KACC) * D + n];
        g_Bh[j] = __float2half_rn(v);
        return;
    }
    int s = j - NPB;
    if (s < NPS) { out[(size_t)NENT * D + s] = spec[s]; return; }
    int z = s - NPS;
    if (z < NENT) g_cur[z] = z * CAP;
}

// ---------------- single-pass bucketed scatter ----------------
__global__ void k_scatter(const int* __restrict__ ei, const int* __restrict__ et) {
    int e = blockIdx.x * blockDim.x + threadIdx.x;
    if (e >= NEDGE) return;
    int src = clampi(ei[e], 0, NENT - 1);
    int dst = clampi(ei[NEDGE + e], 0, NENT - 1);
    int typ = clampi(et[e], 0, NREL - 1);
    int pos = atomicAdd(&g_cur[dst], 1);
    if (pos < (dst + 1) * CAP)                  // clamp vs bucket overflow
        g_pk[pos] = src | (typ << 16);
}

// ---------------- aggregation: warp per node (R12 measured-best form) --------
__global__ __launch_bounds__(256)
void k_agg(const float* __restrict__ comp) {
    __shared__ float comps[NREL * NB];
    __shared__ int   cnts[8][NREL];
    __shared__ float invs[8][NREL];
    int tid = threadIdx.x;
    for (int t = tid; t < NREL * NB; t += 256) comps[t] = comp[t];
    __syncthreads();

    int w = tid >> 5, lane = tid & 31;
    int n = blockIdx.x * 8 + w;
    if (n >= NENT) return;

    int s = n * CAP;
    int e = g_cur[n];
    if (e > s + CAP) e = s + CAP;

    for (int t = lane; t < NREL; t += 32) cnts[w][t] = 0;
    __syncwarp();
    for (int idx = s + lane; idx < e; idx += 32)
        atomicAdd(&cnts[w][(g_pk[idx] >> 16) & 0x3F], 1);
    __syncwarp();
    for (int t = lane; t < NREL; t += 32) {
        int c = cnts[w][t];
        invs[w][t] = (c > 0) ? 1.0f / (float)c : 0.f;
    }
    __syncwarp();

    unsigned long long av01[NB], av23[NB];
    unsigned long long zero = pack2(0.f, 0.f);
#pragma unroll
    for (int b = 0; b < NB; b++) { av01[b] = zero; av23[b] = zero; }

    // software-pipelined edge loop (1-deep prefetch)
    if (s < e) {
        int   pk = g_pk[s];
        uint2 u  = *(const uint2*)(g_xh + (size_t)(pk & 0xFFFF) * D + lane * 4);
        for (int idx = s; idx < e; idx++) {
            int   npk = 0;
            uint2 nu  = make_uint2(0u, 0u);
            if (idx + 1 < e) {
                npk = g_pk[idx + 1];
                nu  = *(const uint2*)(g_xh + (size_t)(npk & 0xFFFF) * D + lane * 4);
            }
            int typ = (pk >> 16) & 0x3F;
            float nm = invs[w][typ];
            float2 x01 = __half22float2(*(__half2*)&u.x);
            float2 x23 = __half22float2(*(__half2*)&u.y);
            unsigned long long px01 = pack2(x01.x, x01.y);
            unsigned long long px23 = pack2(x23.x, x23.y);
#pragma unroll
            for (int b = 0; b < NB; b++) {
                float c = comps[typ * NB + b] * nm;
                unsigned long long cc = pack2(c, c);
                fma2(av01[b], cc, px01);
                fma2(av23[b], cc, px23);
            }
            pk = npk;
            u  = nu;
        }
    }

    size_t rb = (size_t)n * KTOT;
#pragma unroll
    for (int b = 0; b < NB; b++) {
        float2 a01 = unpack2(av01[b]);
        float2 a23 = unpack2(av23[b]);
        uint2 u;
        *(__half2*)&u.x = __float22half2_rn(a01);
        *(__half2*)&u.y = __float22half2_rn(a23);
        *(uint2*)(g_A + rb + b * D + lane * 4) = u;
    }
    *(uint2*)(g_A + rb + KACC + lane * 4) =
        *(const uint2*)(g_xh + (size_t)n * D + lane * 4);
}

// ---------------- fp16 HMMA GEMM: 128x64 tiles, 3 CTAs/SM, 2-stage -----------
// Tile t: m-tile = t>>1 (reverse order), n-half = t&1. Paired CTAs share the
// A tile concurrently -> second read is an L2 hit.
// 8 warps = 4(m) x 2(n), each warp 32x32 -> c = 2x4 frags = 32 regs.
__global__ __launch_bounds__(256, 3)
void k_gemm(const float* __restrict__ bias, float* __restrict__ out) {
    __shared__ __align__(16) __half sA[2][MTILE][SSTR];   // 20 KB
    __shared__ __align__(16) __half sB[2][64][SSTR];      // 10 KB

    int tid = threadIdx.x, wid = tid >> 5, lane = tid & 31;
    int t  = blockIdx.x;
    int m0 = (NTIL - 1 - (t >> 1)) * MTILE;   // reverse: L2-hot A rows first
    int n0 = (t & 1) * 64;
    int wm = wid >> 1;          // 0..3: m offset 32*wm
    int wn = wid & 1;           // 0..1: n offset 32*wn

    float c[2][4][4];
#pragma unroll
    for (int mt = 0; mt < 2; mt++)
#pragma unroll
        for (int nt = 0; nt < 4; nt++)
#pragma unroll
            for (int r = 0; r < 4; r++) c[mt][nt][r] = 0.f;

    // stage loads: A 512 chunks (i=0,1), B 256 chunks (i=2); 16B each
#pragma unroll
    for (int i = 0; i < 2; i++) {
        int cix = tid + i * 256;
        int r = cix >> 2, q = cix & 3;
        cp16(smem_u32(&sA[0][r][q * 8]), g_A + (size_t)(m0 + r) * KTOT + q * 8);
    }
    {
        int r = tid >> 2, q = tid & 3;
        cp16(smem_u32(&sB[0][r][q * 8]), g_Bh + (size_t)(n0 + r) * KTOT + q * 8);
    }
    cp_commit();

    for (int ch = 0; ch < NCH; ch++) {
        int st = ch & 1;
        if (ch + 1 < NCH) {
            int ns = (ch + 1) & 1;
            int kc = (ch + 1) * KC;
#pragma unroll
            for (int i = 0; i < 2; i++) {
                int cix = tid + i * 256;
                int r = cix >> 2, q = cix & 3;
                cp16(smem_u32(&sA[ns][r][q * 8]),
                     g_A + (size_t)(m0 + r) * KTOT + kc + q * 8);
            }
            int r = tid >> 2, q = tid & 3;
            cp16(smem_u32(&sB[ns][r][q * 8]),
                 g_Bh + (size_t)(n0 + r) * KTOT + kc + q * 8);
        }
        cp_commit();
        cp_wait<1>();
        __syncthreads();

#pragma unroll
        for (int ks = 0; ks < 2; ks++) {
            uint32_t a[2][4], b[2][4];
            int arow = wm * 32 + (lane & 15);
            int acol = ks * 16 + (lane >> 4) * 8;
#pragma unroll
            for (int mt = 0; mt < 2; mt++)
                ldsm4(a[mt], smem_u32(&sA[st][arow + mt * 16][acol]));
            int brow = wn * 32 + (lane & 7) + ((lane >> 4) << 3);
            int bcol = ks * 16 + ((lane >> 3) & 1) * 8;
#pragma unroll
            for (int p = 0; p < 2; p++)
                ldsm4(b[p], smem_u32(&sB[st][brow + p * 16][bcol]));
#pragma unroll
            for (int mt = 0; mt < 2; mt++)
#pragma unroll
                for (int nt = 0; nt < 4; nt++)
                    mma_f16(c[mt][nt], a[mt], &b[nt >> 1][(nt & 1) * 2]);
        }
        __syncthreads();
    }

    // epilogue: frag (m16n8): lane owns rows l/4, l/4+8; cols (l&3)*2, +1
#pragma unroll
    for (int mt = 0; mt < 2; mt++) {
#pragma unroll
        for (int nt = 0; nt < 4; nt++) {
            int m = m0 + wm * 32 + mt * 16 + (lane >> 2);
            int n = n0 + wn * 32 + nt * 8 + (lane & 3) * 2;
            float b0 = __ldg(bias + n), b1 = __ldg(bias + n + 1);
            if (m < NENT) {
                float2 v = make_float2(c[mt][nt][0] + b0, c[mt][nt][1] + b1);
                *(float2*)(out + (size_t)m * D + n) = v;
            }
            if (m + 8 < NENT) {
                float2 v = make_float2(c[mt][nt][2] + b0, c[mt][nt][3] + b1);
                *(float2*)(out + (size_t)(m + 8) * D + n) = v;
            }
        }
    }
}

// ---------------- launch ----------------
extern "C" void kernel_launch(void* const* d_in, const int* in_sizes, int n_in,
                              void* d_out, int out_size) {
    const int*   ei    = (const int*)d_in[0];
    const int*   et    = (const int*)d_in[1];
    const float* x     = (const float*)d_in[2];
    const float* basis = (const float*)d_in[3];
    const float* comp  = (const float*)d_in[4];
    const float* root  = (const float*)d_in[5];
    const float* bias  = (const float*)d_in[6];
    const float* spec  = (const float*)d_in[7];
    float*       out   = (float*)d_out;

    k_prep<<<(NPTOT + 255) / 256, 256>>>(x, basis, root, spec, out);
    k_scatter<<<(NEDGE + 255) / 256, 256>>>(ei, et);
    k_agg<<<(NENT + 7) / 8, 256>>>(comp);
    k_gemm<<<NTIL * 2, 256>>>(bias, out);
}

// round 15
// speedup vs baseline: 1.1761x; 1.0678x over previous
#include <cuda_runtime.h>
#include <cuda_fp16.h>
#include <cstdint>

#define D       128
#define NREL    48
#define NB      8
#define NENT    50000
#define NSPEC   64
#define NEDGE   600000
#define CAP     64                  // per-dst bucket capacity (Poisson(12) tail ~0)
#define KACC    1024
#define KTOT    1152
#define MTILE   128
#define NTIL    391                 // ceil(50000/128)
#define MPAD    (NTIL * MTILE)      // 50048
#define KC      32
#define NCH     (KTOT / KC)         // 36
#define SSTR    40                  // row stride (halves): 80B, LDSM conflict-free
#define ABYTES  (MTILE * SSTR * 2)  // 10240 per chunk tile
#define BBYTES  (D * SSTR * 2)      // 10240

// ---------------- device scratch ----------------
__device__ int    g_cur[NENT];                 // bucket cursors (init n*CAP)
__device__ int    g_pk[NENT * CAP];            // bucketed packed (src | type<<16)
__device__ __half g_xh[(size_t)NENT * D];      // x in fp16
// chunk-plane layouts (stride 40, pad cols 32..39 stay zero / never read)
__device__ __align__(128) __half g_A2[(size_t)NCH * MPAD * SSTR];
__device__ __align__(128) __half g_B2[(size_t)NCH * D * SSTR];

__device__ __forceinline__ int clampi(int v, int lo, int hi) {
    return v < lo ? lo : (v > hi ? hi : v);
}
__device__ __forceinline__ uint32_t smem_u32(const void* p) {
    uint32_t a;
    asm("{ .reg .u64 t; cvta.to.shared.u64 t, %1; cvt.u32.u64 %0, t; }"
        : "=r"(a) : "l"(p));
    return a;
}
__device__ __forceinline__ void ldsm4(uint32_t* r, uint32_t addr) {
    asm volatile("ldmatrix.sync.aligned.m8n8.x4.shared.b16 {%0,%1,%2,%3}, [%4];"
        : "=r"(r[0]), "=r"(r[1]), "=r"(r[2]), "=r"(r[3]) : "r"(addr));
}
__device__ __forceinline__ void mma_f16(float* c, const uint32_t* a,
                                        const uint32_t* b) {
    asm volatile(
        "mma.sync.aligned.m16n8k16.row.col.f32.f16.f16.f32 "
        "{%0,%1,%2,%3}, {%4,%5,%6,%7}, {%8,%9}, {%0,%1,%2,%3};"
        : "+f"(c[0]), "+f"(c[1]), "+f"(c[2]), "+f"(c[3])
        : "r"(a[0]), "r"(a[1]), "r"(a[2]), "r"(a[3]), "r"(b[0]), "r"(b[1]));
}
// ---- cp.async.bulk + mbarrier (sm_90 base PTX, legal at compute_103) ----
__device__ __forceinline__ void mbar_init(uint32_t a, uint32_t n) {
    asm volatile("mbarrier.init.shared.b64 [%0], %1;" :: "r"(a), "r"(n) : "memory");
}
__device__ __forceinline__ void mbar_expect_tx(uint32_t a, uint32_t bytes) {
    asm volatile("mbarrier.arrive.expect_tx.shared.b64 _, [%0], %1;"
                 :: "r"(a), "r"(bytes) : "memory");
}
__device__ __forceinline__ void bulk_g2s(uint32_t sdst, const void* gsrc,
                                         uint32_t bytes, uint32_t mbar) {
    asm volatile(
        "cp.async.bulk.shared::cta.global.mbarrier::complete_tx::bytes "
        "[%0], [%1], %2, [%3];"
        :: "r"(sdst), "l"(gsrc), "r"(bytes), "r"(mbar) : "memory");
}
__device__ __forceinline__ void mbar_wait(uint32_t a, uint32_t parity) {
    uint32_t done;
    asm volatile(
        "{\n\t.reg .pred p;\n\t"
        "mbarrier.try_wait.parity.acquire.cta.shared::cta.b64 p, [%1], %2;\n\t"
        "selp.b32 %0, 1, 0, p;\n\t}"
        : "=r"(done) : "r"(a), "r"(parity) : "memory");
    if (!done) {
        asm volatile(
            "{\n\t.reg .pred P1;\n\t"
            "WAIT_LOOP_%=:\n\t"
            "mbarrier.try_wait.parity.acquire.cta.shared::cta.b64 P1, [%0], %1, 0x989680;\n\t"
            "@P1 bra.uni WAIT_DONE_%=;\n\t"
            "bra.uni WAIT_LOOP_%=;\n\t"
            "WAIT_DONE_%=:\n\t}"
            :: "r"(a), "r"(parity) : "memory");
    }
}
// packed f32x2 helpers
__device__ __forceinline__ unsigned long long pack2(float lo, float hi) {
    unsigned long long r;
    asm("mov.b64 %0, {%1, %2};" : "=l"(r) : "f"(lo), "f"(hi));
    return r;
}
__device__ __forceinline__ void fma2(unsigned long long& acc,
                                     unsigned long long a, unsigned long long b) {
    asm("fma.rn.f32x2 %0, %1, %2, %0;" : "+l"(acc) : "l"(a), "l"(b));
}
__device__ __forceinline__ float2 unpack2(unsigned long long v) {
    float lo, hi;
    asm("mov.b64 {%0, %1}, %2;" : "=f"(lo), "=f"(hi) : "l"(v));
    return make_float2(lo, hi);
}

// ---------------- fused prep: x->fp16, B planes, special concat, cursors -----
#define NPX   (NENT * D / 2)
#define NPB   (D * KTOT)
#define NPS   (NSPEC * D)
#define NPZ   (NENT)
#define NPTOT (NPX + NPB + NPS + NPZ)
__global__ void k_prep(const float* __restrict__ x,
                       const float* __restrict__ basis,
                       const float* __restrict__ root,
                       const float* __restrict__ spec,
                       float* __restrict__ out) {
    int i = blockIdx.x * blockDim.x + threadIdx.x;
    if (i < NPX) {
        float2 v = *((const float2*)x + i);
        *((__half2*)g_xh + i) = __float22half2_rn(v);
        return;
    }
    int j = i - NPX;
    if (j < NPB) {
        int n = j / KTOT, k = j % KTOT;
        float v = (k < KACC) ? basis[(size_t)k * D + n]
                             : root[(size_t)(k - KACC) * D + n];
        int ch = k >> 5, off = k & 31;
        g_B2[((size_t)ch * D + n) * SSTR + off] = __float2half_rn(v);
        return;
    }
    int s = j - NPB;
    if (s < NPS) { out[(size_t)NENT * D + s] = spec[s]; return; }
    int z = s - NPS;
    if (z < NENT) g_cur[z] = z * CAP;
}

// ---------------- single-pass bucketed scatter ----------------
__global__ void k_scatter(const int* __restrict__ ei, const int* __restrict__ et) {
    int e = blockIdx.x * blockDim.x + threadIdx.x;
    if (e >= NEDGE) return;
    int src = clampi(ei[e], 0, NENT - 1);
    int dst = clampi(ei[NEDGE + e], 0, NENT - 1);
    int typ = clampi(et[e], 0, NREL - 1);
    int pos = atomicAdd(&g_cur[dst], 1);
    if (pos < (dst + 1) * CAP)
        g_pk[pos] = src | (typ << 16);
}

// ---------------- aggregation: warp per node (R12 form, plane stores) --------
__global__ __launch_bounds__(256)
void k_agg(const float* __restrict__ comp) {
    __shared__ float comps[NREL * NB];
    __shared__ int   cnts[8][NREL];
    __shared__ float invs[8][NREL];
    int tid = threadIdx.x;
    for (int t = tid; t < NREL * NB; t += 256) comps[t] = comp[t];
    __syncthreads();

    int w = tid >> 5, lane = tid & 31;
    int n = blockIdx.x * 8 + w;
    if (n >= NENT) return;

    int s = n * CAP;
    int e = g_cur[n];
    if (e > s + CAP) e = s + CAP;

    for (int t = lane; t < NREL; t += 32) cnts[w][t] = 0;
    __syncwarp();
    for (int idx = s + lane; idx < e; idx += 32)
        atomicAdd(&cnts[w][(g_pk[idx] >> 16) & 0x3F], 1);
    __syncwarp();
    for (int t = lane; t < NREL; t += 32) {
        int c = cnts[w][t];
        invs[w][t] = (c > 0) ? 1.0f / (float)c : 0.f;
    }
    __syncwarp();

    unsigned long long av01[NB], av23[NB];
    unsigned long long zero = pack2(0.f, 0.f);
#pragma unroll
    for (int b = 0; b < NB; b++) { av01[b] = zero; av23[b] = zero; }

    if (s < e) {
        int   pk = g_pk[s];
        uint2 u  = *(const uint2*)(g_xh + (size_t)(pk & 0xFFFF) * D + lane * 4);
        for (int idx = s; idx < e; idx++) {
            int   npk = 0;
            uint2 nu  = make_uint2(0u, 0u);
            if (idx + 1 < e) {
                npk = g_pk[idx + 1];
                nu  = *(const uint2*)(g_xh + (size_t)(npk & 0xFFFF) * D + lane * 4);
            }
            int typ = (pk >> 16) & 0x3F;
            float nm = invs[w][typ];
            float2 x01 = __half22float2(*(__half2*)&u.x);
            float2 x23 = __half22float2(*(__half2*)&u.y);
            unsigned long long px01 = pack2(x01.x, x01.y);
            unsigned long long px23 = pack2(x23.x, x23.y);
#pragma unroll
            for (int b = 0; b < NB; b++) {
                float c = comps[typ * NB + b] * nm;
                unsigned long long cc = pack2(c, c);
                fma2(av01[b], cc, px01);
                fma2(av23[b], cc, px23);
            }
            pk = npk;
            u  = nu;
        }
    }

    // store into chunk planes: k = b*128 + lane*4 -> ch = b*4 + (lane>>3)
    int off = (lane & 7) * 4;
#pragma unroll
    for (int b = 0; b < NB; b++) {
        int ch = b * 4 + (lane >> 3);
        float2 a01 = unpack2(av01[b]);
        float2 a23 = unpack2(av23[b]);
        uint2 u;
        *(__half2*)&u.x = __float22half2_rn(a01);
        *(__half2*)&u.y = __float22half2_rn(a23);
        *(uint2*)(g_A2 + ((size_t)ch * MPAD + n) * SSTR + off) = u;
    }
    // x tail: k = 1024 + lane*4 -> ch = 32 + (lane>>3)
    {
        int ch = 32 + (lane >> 3);
        *(uint2*)(g_A2 + ((size_t)ch * MPAD + n) * SSTR + off) =
            *(const uint2*)(g_xh + (size_t)n * D + lane * 4);
    }
}

// ---------------- fp16 HMMA GEMM: cp.async.bulk double-buffered --------------
__global__ __launch_bounds__(256, 2)
void k_gemm(const float* __restrict__ bias, float* __restrict__ out) {
    __shared__ __align__(128) __half sA[2][MTILE][SSTR];   // 20 KB
    __shared__ __align__(128) __half sB[2][D][SSTR];       // 20 KB
    __shared__ __align__(8) unsigned long long mbar[2];

    int tid = threadIdx.x, wid = tid >> 5, lane = tid & 31;
    int m0 = (NTIL - 1 - blockIdx.x) * MTILE;   // reverse: L2-hot A rows first
    int wm = wid & 1;
    int wn = wid >> 1;
    uint32_t mb0 = smem_u32(&mbar[0]), mb1 = smem_u32(&mbar[1]);

    if (tid == 0) { mbar_init(mb0, 1); mbar_init(mb1, 1); }
    __syncthreads();

    float c[4][4][4];
#pragma unroll
    for (int mt = 0; mt < 4; mt++)
#pragma unroll
        for (int nt = 0; nt < 4; nt++)
#pragma unroll
            for (int r = 0; r < 4; r++) c[mt][nt][r] = 0.f;

    // prologue: issue chunks 0 and 1
    if (tid == 0) {
        mbar_expect_tx(mb0, ABYTES + BBYTES);
        bulk_g2s(smem_u32(&sA[0][0][0]), g_A2 + (size_t)m0 * SSTR, ABYTES, mb0);
        bulk_g2s(smem_u32(&sB[0][0][0]), g_B2, BBYTES, mb0);
        mbar_expect_tx(mb1, ABYTES + BBYTES);
        bulk_g2s(smem_u32(&sA[1][0][0]),
                 g_A2 + ((size_t)1 * MPAD + m0) * SSTR, ABYTES, mb1);
        bulk_g2s(smem_u32(&sB[1][0][0]), g_B2 + (size_t)1 * D * SSTR, BBYTES, mb1);
    }

    for (int ch = 0; ch < NCH; ch++) {
        int st = ch & 1;
        mbar_wait(st ? mb1 : mb0, (uint32_t)((ch >> 1) & 1));

        uint32_t a[4][4], b[2][4];
        int arow = wm * 64 + (lane & 15);
        int acol = (lane >> 4) * 8;
        int brow = wn * 32 + (lane & 7) + ((lane >> 4) << 3);
        int bcol = ((lane >> 3) & 1) * 8;
#pragma unroll
        for (int ks = 0; ks < 2; ks++) {
#pragma unroll
            for (int mt = 0; mt < 4; mt++)
                ldsm4(a[mt], smem_u32(&sA[st][arow + mt * 16][ks * 16 + acol]));
#pragma unroll
            for (int p = 0; p < 2; p++)
                ldsm4(b[p], smem_u32(&sB[st][brow + p * 16][ks * 16 + bcol]));
#pragma unroll
            for (int mt = 0; mt < 4; mt++)
#pragma unroll
                for (int nt = 0; nt < 4; nt++)
                    mma_f16(c[mt][nt], a[mt], &b[nt >> 1][(nt & 1) * 2]);
        }
        __syncthreads();   // all warps done with stage st before refill

        int nc = ch + 2;
        if (nc < NCH && tid == 0) {
            uint32_t mb = st ? mb1 : mb0;
            mbar_expect_tx(mb, ABYTES + BBYTES);
            bulk_g2s(smem_u32(&sA[st][0][0]),
                     g_A2 + ((size_t)nc * MPAD + m0) * SSTR, ABYTES, mb);
            bulk_g2s(smem_u32(&sB[st][0][0]),
                     g_B2 + (size_t)nc * D * SSTR, BBYTES, mb);
        }
    }

    // epilogue: frag (m16n8): lane owns rows l/4, l/4+8; cols (l&3)*2, +1
#pragma unroll
    for (int mt = 0; mt < 4; mt++) {
#pragma unroll
        for (int nt = 0; nt < 4; nt++) {
            int m = m0 + wm * 64 + mt * 16 + (lane >> 2);
            int n = wn * 32 + nt * 8 + (lane & 3) * 2;
            float b0 = __ldg(bias + n), b1 = __ldg(bias + n + 1);
            if (m < NENT) {
                float2 v = make_float2(c[mt][nt][0] + b0, c[mt][nt][1] + b1);
                *(float2*)(out + (size_t)m * D + n) = v;
            }
            if (m + 8 < NENT) {
                float2 v = make_float2(c[mt][nt][2] + b0, c[mt][nt][3] + b1);
                *(float2*)(out + (size_t)(m + 8) * D + n) = v;
            }
        }
    }
}

// ---------------- launch ----------------
extern "C" void kernel_launch(void* const* d_in, const int* in_sizes, int n_in,
                              void* d_out, int out_size) {
    const int*   ei    = (const int*)d_in[0];
    const int*   et    = (const int*)d_in[1];
    const float* x     = (const float*)d_in[2];
    const float* basis = (const float*)d_in[3];
    const float* comp  = (const float*)d_in[4];
    const float* root  = (const float*)d_in[5];
    const float* bias  = (const float*)d_in[6];
    const float* spec  = (const float*)d_in[7];
    float*       out   = (float*)d_out;

    k_prep<<<(NPTOT + 255) / 256, 256>>>(x, basis, root, spec, out);
    k_scatter<<<(NEDGE + 255) / 256, 256>>>(ei, et);
    k_agg<<<(NENT + 7) / 8, 256>>>(comp);
    k_gemm<<<NTIL, 256>>>(bias, out);
}